// round 6
// baseline (speedup 1.0000x reference)
#include <cuda_runtime.h>
#include <cuda_bf16.h>

// Problem dims
#define BATCH 8192
#define SEQ   128
#define EDIM  300
#define K1    600     // 2*EDIM
#define H1D   2048
#define H2D   2048
#define CDIM  1221
#define PADTOK 1

// Scratch (allocation-free rule: __device__ globals)
__device__ float g_feat[(size_t)BATCH * K1];
__device__ float g_h1[(size_t)BATCH * H1D];
__device__ float g_h2[(size_t)BATCH * H2D];

// ---------------------------------------------------------------------------
// Stage 1: embedding gather + masked mean + first-token feature
// One CTA per batch element. 256 threads; thread t owns dims {t, t+256}.
// x is [S, B] row-major (x[s*B + b]).
// ---------------------------------------------------------------------------
__global__ void __launch_bounds__(256) embed_mean_kernel(
    const int* __restrict__ x, const float* __restrict__ emb,
    float* __restrict__ feat)
{
    const int b = blockIdx.x;
    __shared__ int s_last;

    if (threadIdx.x == 0) {
        int last = SEQ - 1;
        for (int s = SEQ - 1; s >= 0; --s) {
            if (x[s * BATCH + b] != PADTOK) { last = s; break; }
        }
        s_last = last;
    }
    __syncthreads();

    const int last = s_last;
    const float inv = 1.0f / (float)(last + 1);
    const int t = threadIdx.x;

    float acc0 = 0.0f, acc1 = 0.0f;
    for (int s = 0; s <= last; ++s) {
        const float* row = emb + (size_t)x[s * BATCH + b] * EDIM;
        acc0 += row[t];
        if (t + 256 < EDIM) acc1 += row[t + 256];
    }

    const float* row0 = emb + (size_t)x[b] * EDIM;  // s = 0
    float* fb = feat + (size_t)b * K1;
    fb[t]        = row0[t];
    fb[EDIM + t] = acc0 * inv;
    if (t + 256 < EDIM) {
        fb[t + 256]        = row0[t + 256];
        fb[EDIM + t + 256] = acc1 * inv;
    }
}

// ---------------------------------------------------------------------------
// Stage 2/3/4: Out[M,N] = act(A[M,K] @ W[N,K]^T + bias)
// Double-buffered tiled SGEMM: 128x128 block tile, BK=8, 8x8 microtile,
// float4 global loads prefetched into registers one tile ahead, As stored
// transposed. One __syncthreads per K-tile.
// M = 8192 (mult of 128), K in {600, 2048} (mult of 8), N in {2048, 1221}.
// ---------------------------------------------------------------------------
#define BM 128
#define BN 128
#define BKT 8
#define TM 8
#define TN 8

__global__ void __launch_bounds__(256) sgemm_bias_kernel(
    const float* __restrict__ A, const float* __restrict__ W,
    const float* __restrict__ bias, float* __restrict__ Out,
    int M, int N, int K, int do_relu)
{
    __shared__ float As[2][BKT][BM];
    __shared__ float Bs[2][BKT][BN + 4];

    const int tid = threadIdx.x;
    const int tx = tid & 15;   // 16 col groups
    const int ty = tid >> 4;   // 16 row groups

    const int mBase = blockIdx.y * BM;
    const int nBase = blockIdx.x * BN;

    // global-load assignment: one float4 from A and one from W per K-tile
    const int lrow = tid >> 1;          // 0..127
    const int lk4  = (tid & 1) * 4;     // 0 or 4

    const float* Aptr = A + (size_t)(mBase + lrow) * K + lk4;
    const int wn = nBase + lrow;
    const bool wvalid = wn < N;
    const float* Wptr = W + (size_t)(wvalid ? wn : 0) * K + lk4;

    float acc[TM][TN];
    #pragma unroll
    for (int i = 0; i < TM; ++i)
        #pragma unroll
        for (int j = 0; j < TN; ++j) acc[i][j] = 0.0f;

    // Preload tile 0 into buffer 0
    float4 av = *reinterpret_cast<const float4*>(Aptr);
    float4 wv = wvalid ? *reinterpret_cast<const float4*>(Wptr)
                       : make_float4(0.f, 0.f, 0.f, 0.f);
    As[0][lk4 + 0][lrow] = av.x;
    As[0][lk4 + 1][lrow] = av.y;
    As[0][lk4 + 2][lrow] = av.z;
    As[0][lk4 + 3][lrow] = av.w;
    Bs[0][lk4 + 0][lrow] = wv.x;
    Bs[0][lk4 + 1][lrow] = wv.y;
    Bs[0][lk4 + 2][lrow] = wv.z;
    Bs[0][lk4 + 3][lrow] = wv.w;
    __syncthreads();

    int buf = 0;
    for (int k0 = 0; k0 < K; k0 += BKT) {
        const int kNext = k0 + BKT;
        const bool hasNext = kNext < K;

        // Prefetch next tile into registers (issue loads early; latency
        // overlaps the FMA block below)
        float4 avn, wvn;
        if (hasNext) {
            avn = *reinterpret_cast<const float4*>(Aptr + kNext);
            wvn = wvalid ? *reinterpret_cast<const float4*>(Wptr + kNext)
                         : make_float4(0.f, 0.f, 0.f, 0.f);
        }

        // Compute on current buffer
        #pragma unroll
        for (int k = 0; k < BKT; ++k) {
            float ra[TM], rb[TN];
            #pragma unroll
            for (int i = 0; i < TM; ++i) ra[i] = As[buf][k][ty * TM + i];
            #pragma unroll
            for (int j = 0; j < TN; ++j) rb[j] = Bs[buf][k][tx * TN + j];
            #pragma unroll
            for (int i = 0; i < TM; ++i)
                #pragma unroll
                for (int j = 0; j < TN; ++j)
                    acc[i][j] = fmaf(ra[i], rb[j], acc[i][j]);
        }

        // Store prefetched tile into alternate buffer
        if (hasNext) {
            const int nb = buf ^ 1;
            As[nb][lk4 + 0][lrow] = avn.x;
            As[nb][lk4 + 1][lrow] = avn.y;
            As[nb][lk4 + 2][lrow] = avn.z;
            As[nb][lk4 + 3][lrow] = avn.w;
            Bs[nb][lk4 + 0][lrow] = wvn.x;
            Bs[nb][lk4 + 1][lrow] = wvn.y;
            Bs[nb][lk4 + 2][lrow] = wvn.z;
            Bs[nb][lk4 + 3][lrow] = wvn.w;
            __syncthreads();
            buf = nb;
        }
    }

    // epilogue: bias + optional relu, guarded on N
    #pragma unroll
    for (int i = 0; i < TM; ++i) {
        const int m = mBase + ty * TM + i;
        #pragma unroll
        for (int j = 0; j < TN; ++j) {
            const int n = nBase + tx * TN + j;
            if (n < N) {
                float v = acc[i][j] + bias[n];
                if (do_relu) v = fmaxf(v, 0.0f);
                Out[(size_t)m * N + n] = v;
            }
        }
    }
}

// ---------------------------------------------------------------------------
extern "C" void kernel_launch(void* const* d_in, const int* in_sizes, int n_in,
                              void* d_out, int out_size)
{
    const int*   x     = (const int*)  d_in[0];
    const float* emb   = (const float*)d_in[1];
    const float* W1    = (const float*)d_in[2];
    const float* b1    = (const float*)d_in[3];
    const float* W2    = (const float*)d_in[4];
    const float* b2    = (const float*)d_in[5];
    const float* W_out = (const float*)d_in[6];
    const float* b_out = (const float*)d_in[7];
    float* out = (float*)d_out;

    float *feat, *h1, *h2;
    cudaGetSymbolAddress((void**)&feat, g_feat);
    cudaGetSymbolAddress((void**)&h1,   g_h1);
    cudaGetSymbolAddress((void**)&h2,   g_h2);

    // Stage 1: features
    embed_mean_kernel<<<BATCH, 256>>>(x, emb, feat);

    // Stage 2: h1 = relu(feat @ W1^T + b1)   [8192 x 2048], K=600
    {
        dim3 grid(H1D / BN, BATCH / BM);
        sgemm_bias_kernel<<<grid, 256>>>(feat, W1, b1, h1, BATCH, H1D, K1, 1);
    }
    // Stage 3: h2 = relu(h1 @ W2^T + b2)     [8192 x 2048], K=2048
    {
        dim3 grid(H2D / BN, BATCH / BM);
        sgemm_bias_kernel<<<grid, 256>>>(h1, W2, b2, h2, BATCH, H2D, H1D, 1);
    }
    // Stage 4: out = h2 @ W_out^T + b_out    [8192 x 1221], K=2048
    {
        dim3 grid((CDIM + BN - 1) / BN, BATCH / BM);
        sgemm_bias_kernel<<<grid, 256>>>(h2, W_out, b_out, out, BATCH, CDIM, H2D, 0);
    }
}

// round 7
// speedup vs baseline: 1.7850x; 1.7850x over previous
#include <cuda_runtime.h>
#include <cuda_bf16.h>
#include <cstdint>

// Problem dims
#define BATCH 8192
#define SEQ   128
#define EDIM  300
#define K1    600     // 2*EDIM
#define K1P   640     // padded to multiple of 32 (BK)
#define H1D   2048
#define H2D   2048
#define CDIM  1221
#define PADTOK 1

typedef __nv_bfloat16 bf16;

// ---------------------------------------------------------------------------
// Scratch (__device__ globals; zero-initialized at load, so K-padding columns
// that are never written stay zero forever)
// ---------------------------------------------------------------------------
__device__ bf16 g_feat_hi[(size_t)BATCH * K1P];
__device__ bf16 g_feat_lo[(size_t)BATCH * K1P];
__device__ bf16 g_h1_hi[(size_t)BATCH * H1D];
__device__ bf16 g_h1_lo[(size_t)BATCH * H1D];
__device__ bf16 g_h2_hi[(size_t)BATCH * H2D];
__device__ bf16 g_h2_lo[(size_t)BATCH * H2D];
__device__ bf16 g_W1_hi[(size_t)H1D * K1P];
__device__ bf16 g_W1_lo[(size_t)H1D * K1P];
__device__ bf16 g_W2_hi[(size_t)H2D * H1D];
__device__ bf16 g_W2_lo[(size_t)H2D * H1D];
__device__ bf16 g_Wo_hi[(size_t)CDIM * H2D];
__device__ bf16 g_Wo_lo[(size_t)CDIM * H2D];

__device__ __forceinline__ void split2(float v, bf16* hi, bf16* lo) {
    bf16 h = __float2bfloat16(v);
    *hi = h;
    *lo = __float2bfloat16(v - __bfloat162float(h));
}

// ---------------------------------------------------------------------------
// Weight split: W[N][K] fp32 -> hi/lo bf16 [N][Kp]
// ---------------------------------------------------------------------------
__global__ void split_mat_kernel(const float* __restrict__ W,
                                 bf16* __restrict__ hi, bf16* __restrict__ lo,
                                 int N, int K, int Kp)
{
    for (int i = blockIdx.x * blockDim.x + threadIdx.x; i < N * K;
         i += gridDim.x * blockDim.x) {
        int r = i / K, c = i - r * K;
        split2(W[i], &hi[(size_t)r * Kp + c], &lo[(size_t)r * Kp + c]);
    }
}

// ---------------------------------------------------------------------------
// Stage 1: embedding gather + masked mean + first-token feature -> split bf16
// One CTA per batch element. x is [S, B] row-major.
// ---------------------------------------------------------------------------
__global__ void __launch_bounds__(256) embed_mean_kernel(
    const int* __restrict__ x, const float* __restrict__ emb,
    bf16* __restrict__ fhi, bf16* __restrict__ flo)
{
    const int b = blockIdx.x;
    __shared__ int s_last;

    if (threadIdx.x == 0) {
        int last = SEQ - 1;
        for (int s = SEQ - 1; s >= 0; --s) {
            if (x[s * BATCH + b] != PADTOK) { last = s; break; }
        }
        s_last = last;
    }
    __syncthreads();

    const int last = s_last;
    const float inv = 1.0f / (float)(last + 1);
    const int t = threadIdx.x;

    float acc0 = 0.0f, acc1 = 0.0f;
    for (int s = 0; s <= last; ++s) {
        const float* row = emb + (size_t)x[s * BATCH + b] * EDIM;
        if (t < EDIM) acc0 += row[t];
        if (t + 256 < EDIM) acc1 += row[t + 256];
    }

    const float* row0 = emb + (size_t)x[b] * EDIM;  // s = 0
    bf16* fh = fhi + (size_t)b * K1P;
    bf16* fl = flo + (size_t)b * K1P;
    if (t < EDIM) {
        split2(row0[t],     &fh[t],        &fl[t]);
        split2(acc0 * inv,  &fh[EDIM + t], &fl[EDIM + t]);
    }
    if (t + 256 < EDIM) {
        split2(row0[t + 256],  &fh[t + 256],        &fl[t + 256]);
        split2(acc1 * inv,     &fh[EDIM + t + 256], &fl[EDIM + t + 256]);
    }
}

// ---------------------------------------------------------------------------
// Tensor-core split-bf16 GEMM:
//   C[M,N] = A[M,K] @ W[N,K]^T  via  AhiBhi + AhiBlo + AloBhi (fp32 accum)
// CTA tile 128x128, BK=32, 8 warps (2x4), warp tile 64x32, mma.m16n8k16.
// Double-buffered smem, rows padded to 40 bf16 (80B) -> conflict-free ldmatrix.
// ---------------------------------------------------------------------------
#define BM 128
#define BN 128
#define BK 32
#define LDSH 40   // smem row stride in bf16 elements (80 bytes)

__device__ __forceinline__ void ldsm4(uint32_t& r0, uint32_t& r1,
                                      uint32_t& r2, uint32_t& r3, uint32_t addr)
{
    asm volatile("ldmatrix.sync.aligned.m8n8.x4.shared.b16 {%0,%1,%2,%3}, [%4];"
                 : "=r"(r0), "=r"(r1), "=r"(r2), "=r"(r3) : "r"(addr));
}

__device__ __forceinline__ void mma16816(float* c, const uint32_t* a,
                                         const uint32_t* b)
{
    asm volatile(
        "mma.sync.aligned.m16n8k16.row.col.f32.bf16.bf16.f32 "
        "{%0,%1,%2,%3}, {%4,%5,%6,%7}, {%8,%9}, {%0,%1,%2,%3};"
        : "+f"(c[0]), "+f"(c[1]), "+f"(c[2]), "+f"(c[3])
        : "r"(a[0]), "r"(a[1]), "r"(a[2]), "r"(a[3]), "r"(b[0]), "r"(b[1]));
}

template<bool SPLIT_RELU_OUT>
__global__ void __launch_bounds__(256) gemm_bf16s_kernel(
    const bf16* __restrict__ aHi, const bf16* __restrict__ aLo,
    const bf16* __restrict__ bHi, const bf16* __restrict__ bLo,
    const float* __restrict__ bias,
    float* __restrict__ outF, bf16* __restrict__ outHi, bf16* __restrict__ outLo,
    int N, int K)
{
    __shared__ bf16 As[2][BM * LDSH];
    __shared__ bf16 Bs[2][BM * LDSH];

    const int tid  = threadIdx.x;
    const int lane = tid & 31;
    const int warp = tid >> 5;
    const int warpM = (warp >> 2) * 64;   // 2 warps in M
    const int warpN = (warp & 3) * 32;    // 4 warps in N
    const int mBase = blockIdx.y * BM;
    const int nBase = blockIdx.x * BN;

    const int KT = K / BK;
    const int NT = 3 * KT;

    const bf16* aB[3] = { aHi, aHi, aLo };
    const bf16* bB[3] = { bHi, bLo, bHi };

    // global->smem fill mapping: thread handles rows frow and frow+64,
    // 16B chunk (tid&3) within the 64B K-row
    const int frow = tid >> 2;            // 0..63
    const int fcol = (tid & 3) * 8;       // bf16 offset 0/8/16/24
    const size_t arow0 = (size_t)(mBase + frow) * K + fcol;
    const size_t arow1 = (size_t)(mBase + frow + 64) * K + fcol;
    const int nrow0 = nBase + frow, nrow1 = nBase + frow + 64;
    const bool v0 = nrow0 < N, v1 = nrow1 < N;
    const size_t brow0 = (size_t)(v0 ? nrow0 : 0) * K + fcol;
    const size_t brow1 = (size_t)(v1 ? nrow1 : 0) * K + fcol;
    const int sIdx0 = frow * LDSH + fcol;
    const int sIdx1 = (frow + 64) * LDSH + fcol;

    uint32_t sAb[2], sBb[2];
    sAb[0] = (uint32_t)__cvta_generic_to_shared(&As[0][0]);
    sAb[1] = (uint32_t)__cvta_generic_to_shared(&As[1][0]);
    sBb[0] = (uint32_t)__cvta_generic_to_shared(&Bs[0][0]);
    sBb[1] = (uint32_t)__cvta_generic_to_shared(&Bs[1][0]);

    // ldmatrix per-lane address components (bf16 element offsets)
    const int g  = lane >> 3;
    const int ri = lane & 7;
    const int aOff = (warpM + ((g & 1) << 3) + ri) * LDSH + ((g >> 1) << 3);
    const int bOff = (warpN + ((g >> 1) << 3) + ri) * LDSH + ((g & 1) << 3);

    float acc[4][4][4];
    #pragma unroll
    for (int mi = 0; mi < 4; ++mi)
        #pragma unroll
        for (int ni = 0; ni < 4; ++ni)
            #pragma unroll
            for (int q = 0; q < 4; ++q) acc[mi][ni][q] = 0.0f;

    uint4 pa0, pa1, pb0, pb1;
    {   // tile 0
        const bf16* ab = aB[0]; const bf16* bb = bB[0];
        pa0 = *(const uint4*)(ab + arow0);
        pa1 = *(const uint4*)(ab + arow1);
        pb0 = v0 ? *(const uint4*)(bb + brow0) : make_uint4(0, 0, 0, 0);
        pb1 = v1 ? *(const uint4*)(bb + brow1) : make_uint4(0, 0, 0, 0);
    }
    *(uint4*)&As[0][sIdx0] = pa0;
    *(uint4*)&As[0][sIdx1] = pa1;
    *(uint4*)&Bs[0][sIdx0] = pb0;
    *(uint4*)&Bs[0][sIdx1] = pb1;
    __syncthreads();

    int buf = 0;
    for (int t = 0; t < NT; ++t) {
        // prefetch next tile into registers
        if (t + 1 < NT) {
            const int tn = t + 1;
            const int p  = tn / KT;
            const size_t kk = (size_t)(tn - p * KT) * BK;
            const bf16* ab = aB[p]; const bf16* bb = bB[p];
            pa0 = *(const uint4*)(ab + arow0 + kk);
            pa1 = *(const uint4*)(ab + arow1 + kk);
            pb0 = v0 ? *(const uint4*)(bb + brow0 + kk) : make_uint4(0, 0, 0, 0);
            pb1 = v1 ? *(const uint4*)(bb + brow1 + kk) : make_uint4(0, 0, 0, 0);
        }

        const uint32_t sA = sAb[buf], sB = sBb[buf];
        #pragma unroll
        for (int kh = 0; kh < 2; ++kh) {
            const int kc = kh * 16;
            uint32_t afr[4][4];
            #pragma unroll
            for (int mi = 0; mi < 4; ++mi)
                ldsm4(afr[mi][0], afr[mi][1], afr[mi][2], afr[mi][3],
                      sA + (uint32_t)(aOff + mi * 16 * LDSH + kc) * 2u);
            uint32_t bfr[4][2];
            #pragma unroll
            for (int nj = 0; nj < 2; ++nj) {
                uint32_t r0, r1, r2, r3;
                ldsm4(r0, r1, r2, r3,
                      sB + (uint32_t)(bOff + nj * 16 * LDSH + kc) * 2u);
                bfr[2 * nj][0] = r0; bfr[2 * nj][1] = r1;
                bfr[2 * nj + 1][0] = r2; bfr[2 * nj + 1][1] = r3;
            }
            #pragma unroll
            for (int mi = 0; mi < 4; ++mi)
                #pragma unroll
                for (int ni = 0; ni < 4; ++ni)
                    mma16816(acc[mi][ni], afr[mi], bfr[ni]);
        }

        if (t + 1 < NT) {
            const int nb = buf ^ 1;
            *(uint4*)&As[nb][sIdx0] = pa0;
            *(uint4*)&As[nb][sIdx1] = pa1;
            *(uint4*)&Bs[nb][sIdx0] = pb0;
            *(uint4*)&Bs[nb][sIdx1] = pb1;
            __syncthreads();
            buf = nb;
        }
    }

    // epilogue: c-fragment m16n8: (rr,cc),(rr,cc+1),(rr+8,cc),(rr+8,cc+1)
    const int rr = lane >> 2;
    const int cc = (lane & 3) * 2;
    #pragma unroll
    for (int mi = 0; mi < 4; ++mi) {
        #pragma unroll
        for (int ni = 0; ni < 4; ++ni) {
            const int r0g = mBase + warpM + mi * 16 + rr;
            const int c0g = nBase + warpN + ni * 8 + cc;
            const float* a = acc[mi][ni];
            #pragma unroll
            for (int q = 0; q < 4; ++q) {
                const int r = r0g + (q >> 1) * 8;
                const int c = c0g + (q & 1);
                if (SPLIT_RELU_OUT) {
                    float v = fmaxf(a[q] + bias[c], 0.0f);
                    split2(v, &outHi[(size_t)r * N + c], &outLo[(size_t)r * N + c]);
                } else {
                    if (c < N) outF[(size_t)r * N + c] = a[q] + bias[c];
                }
            }
        }
    }
}

// ---------------------------------------------------------------------------
extern "C" void kernel_launch(void* const* d_in, const int* in_sizes, int n_in,
                              void* d_out, int out_size)
{
    const int*   x     = (const int*)  d_in[0];
    const float* emb   = (const float*)d_in[1];
    const float* W1    = (const float*)d_in[2];
    const float* b1    = (const float*)d_in[3];
    const float* W2    = (const float*)d_in[4];
    const float* b2    = (const float*)d_in[5];
    const float* W_out = (const float*)d_in[6];
    const float* b_out = (const float*)d_in[7];
    float* out = (float*)d_out;

    bf16 *fhi, *flo, *h1hi, *h1lo, *h2hi, *h2lo;
    bf16 *w1hi, *w1lo, *w2hi, *w2lo, *wohi, *wolo;
    cudaGetSymbolAddress((void**)&fhi,  g_feat_hi);
    cudaGetSymbolAddress((void**)&flo,  g_feat_lo);
    cudaGetSymbolAddress((void**)&h1hi, g_h1_hi);
    cudaGetSymbolAddress((void**)&h1lo, g_h1_lo);
    cudaGetSymbolAddress((void**)&h2hi, g_h2_hi);
    cudaGetSymbolAddress((void**)&h2lo, g_h2_lo);
    cudaGetSymbolAddress((void**)&w1hi, g_W1_hi);
    cudaGetSymbolAddress((void**)&w1lo, g_W1_lo);
    cudaGetSymbolAddress((void**)&w2hi, g_W2_hi);
    cudaGetSymbolAddress((void**)&w2lo, g_W2_lo);
    cudaGetSymbolAddress((void**)&wohi, g_Wo_hi);
    cudaGetSymbolAddress((void**)&wolo, g_Wo_lo);

    // Weight splits (cheap; every call to stay deterministic/stateless)
    split_mat_kernel<<<1024, 256>>>(W1,    w1hi, w1lo, H1D,  K1,  K1P);
    split_mat_kernel<<<1024, 256>>>(W2,    w2hi, w2lo, H2D,  H1D, H1D);
    split_mat_kernel<<<1024, 256>>>(W_out, wohi, wolo, CDIM, H2D, H2D);

    // Stage 1: features (split bf16)
    embed_mean_kernel<<<BATCH, 256>>>(x, emb, fhi, flo);

    // Stage 2: h1 = relu(feat @ W1^T + b1)  [8192 x 2048], K=640 (padded)
    {
        dim3 grid(H1D / BN, BATCH / BM);
        gemm_bf16s_kernel<true><<<grid, 256>>>(fhi, flo, w1hi, w1lo, b1,
                                               nullptr, h1hi, h1lo, H1D, K1P);
    }
    // Stage 3: h2 = relu(h1 @ W2^T + b2)    [8192 x 2048], K=2048
    {
        dim3 grid(H2D / BN, BATCH / BM);
        gemm_bf16s_kernel<true><<<grid, 256>>>(h1hi, h1lo, w2hi, w2lo, b2,
                                               nullptr, h2hi, h2lo, H2D, H1D);
    }
    // Stage 4: out = h2 @ W_out^T + b_out   [8192 x 1221], K=2048, fp32 out
    {
        dim3 grid((CDIM + BN - 1) / BN, BATCH / BM);
        gemm_bf16s_kernel<false><<<grid, 256>>>(h2hi, h2lo, wohi, wolo, b_out,
                                                out, nullptr, nullptr, CDIM, H2D);
    }
}